// round 10
// baseline (speedup 1.0000x reference)
#include <cuda_runtime.h>
#include <cuda_bf16.h>
#include <math_constants.h>

// SoftDiceLoss: probs [64,1,512,512] f32, targets same. Scalar f32 output.
//
// Fused single-kernel version: each CTA reduces its slice to a partial,
// last CTA (threadfence-reduction pattern) merges all partials, computes
// the loss, writes the scalar, and resets the arrival counter.
//
// Per-sample monoid:
//   sums: sum_p, sum_t, sum_pt, cnt_le (count p<=0.5)
//   max-with-counts: (m, n1, n0): m = running max of t,
//     n1 = #{t==m && p>0.5}, n0 = #{t==m && p<=0.5}
// corr = n1 + cnt_le - n0;  acc = corr / C (C=1);
// dice = 2*(sum_pt+1)/(sum_p+sum_t+1); score = (acc==1) ? 1 : dice;
// loss = mean_b(1 - score).

static constexpr int B        = 64;
static constexpr int NPS      = 512 * 512;   // elements per sample (C=1)
static constexpr int BPS      = 16;          // blocks per sample -> 1024 CTAs
static constexpr int GRID     = B * BPS;
static constexpr int THREADS  = 256;
static constexpr int PER_BLK  = NPS / BPS;            // 16384
static constexpr int VEC_PER_THREAD = PER_BLK / (THREADS * 4);  // 16 float4

// partials split for vectorized cross-SM reads:
//   f4 = {sum_p, sum_t, sum_pt, m}, i4 = {cnt_le, n1, n0, pad}
__device__ float4 g_pf4[GRID];
__device__ int4   g_pi4[GRID];
__device__ unsigned int g_count = 0;

__device__ __forceinline__ void merge_max(float& m, int& n1, int& n0,
                                          float mo, int n1o, int n0o) {
    if (mo > m)        { m = mo; n1 = n1o; n0 = n0o; }
    else if (mo == m)  { n1 += n1o; n0 += n0o; }
}

__global__ __launch_bounds__(THREADS)
void sdl_fused(const float* __restrict__ probs,
               const float* __restrict__ targets,
               float* __restrict__ out) {
    const int s  = blockIdx.x / BPS;       // sample
    const int bi = blockIdx.x % BPS;       // block within sample
    const int tid = threadIdx.x;

    const float4* p4 = reinterpret_cast<const float4*>(probs   + (size_t)s * NPS + (size_t)bi * PER_BLK);
    const float4* t4 = reinterpret_cast<const float4*>(targets + (size_t)s * NPS + (size_t)bi * PER_BLK);

    float sum_p = 0.f, sum_t = 0.f, sum_pt = 0.f;
    int   cnt_le = 0;
    float m = -CUDART_INF_F;
    int   n1 = 0, n0 = 0;

    #pragma unroll 8
    for (int k = 0; k < VEC_PER_THREAD; k++) {
        float4 pv = p4[tid + k * THREADS];
        float4 tv = t4[tid + k * THREADS];
        const float pa[4] = {pv.x, pv.y, pv.z, pv.w};
        const float ta[4] = {tv.x, tv.y, tv.z, tv.w};
        #pragma unroll
        for (int j = 0; j < 4; j++) {
            float p = pa[j], t = ta[j];
            sum_p  += p;
            sum_t  += t;
            sum_pt += p * t;
            bool sr = (p > 0.5f);
            cnt_le += sr ? 0 : 1;
            bool gt = (t > m);
            m  = gt ? t : m;
            n1 = gt ? 0 : n1;
            n0 = gt ? 0 : n0;
            bool eq = (t == m);
            n1 += (eq &&  sr) ? 1 : 0;
            n0 += (eq && !sr) ? 1 : 0;
        }
    }

    // warp butterfly reduce
    #pragma unroll
    for (int off = 16; off > 0; off >>= 1) {
        sum_p  += __shfl_xor_sync(0xffffffffu, sum_p,  off);
        sum_t  += __shfl_xor_sync(0xffffffffu, sum_t,  off);
        sum_pt += __shfl_xor_sync(0xffffffffu, sum_pt, off);
        cnt_le += __shfl_xor_sync(0xffffffffu, cnt_le, off);
        float mo  = __shfl_xor_sync(0xffffffffu, m,  off);
        int   n1o = __shfl_xor_sync(0xffffffffu, n1, off);
        int   n0o = __shfl_xor_sync(0xffffffffu, n0, off);
        merge_max(m, n1, n0, mo, n1o, n0o);
    }

    __shared__ float4 shf[THREADS / 32];
    __shared__ int4   shi[THREADS / 32];
    const int wid = tid / 32, lid = tid % 32;
    if (lid == 0) {
        shf[wid] = make_float4(sum_p, sum_t, sum_pt, m);
        shi[wid] = make_int4(cnt_le, n1, n0, 0);
    }
    __syncthreads();

    if (wid == 0) {
        constexpr int NW = THREADS / 32;
        float4 af; int4 ai;
        if (lid < NW) { af = shf[lid]; ai = shi[lid]; }
        else { af = make_float4(0.f, 0.f, 0.f, -CUDART_INF_F); ai = make_int4(0, 0, 0, 0); }
        sum_p = af.x; sum_t = af.y; sum_pt = af.z; m = af.w;
        cnt_le = ai.x; n1 = ai.y; n0 = ai.z;
        #pragma unroll
        for (int off = NW / 2; off > 0; off >>= 1) {
            sum_p  += __shfl_xor_sync(0xffffffffu, sum_p,  off);
            sum_t  += __shfl_xor_sync(0xffffffffu, sum_t,  off);
            sum_pt += __shfl_xor_sync(0xffffffffu, sum_pt, off);
            cnt_le += __shfl_xor_sync(0xffffffffu, cnt_le, off);
            float mo  = __shfl_xor_sync(0xffffffffu, m,  off);
            int   n1o = __shfl_xor_sync(0xffffffffu, n1, off);
            int   n0o = __shfl_xor_sync(0xffffffffu, n0, off);
            merge_max(m, n1, n0, mo, n1o, n0o);
        }
    }

    // ---- publish partial, detect last CTA ----
    __shared__ bool isLast;
    if (tid == 0) {
        g_pf4[blockIdx.x] = make_float4(sum_p, sum_t, sum_pt, m);
        g_pi4[blockIdx.x] = make_int4(cnt_le, n1, n0, 0);
        __threadfence();
        unsigned int old = atomicAdd(&g_count, 1u);
        isLast = (old == (unsigned int)(GRID - 1));
    }
    __syncthreads();

    if (!isLast) return;

    // ---- final merge: thread b (<64) merges its sample's 16 partials ----
    __threadfence();  // make other CTAs' partial writes visible

    float v = 0.f;
    const int b = tid;
    if (b < B) {
        float fsp = 0.f, fst = 0.f, fspt = 0.f;
        int   fcl = 0;
        float fm = -CUDART_INF_F;
        int   fn1 = 0, fn0 = 0;
        #pragma unroll
        for (int i = 0; i < BPS; i++) {
            float4 pf = __ldcg(&g_pf4[b * BPS + i]);
            int4   pi = __ldcg(&g_pi4[b * BPS + i]);
            fsp  += pf.x;
            fst  += pf.y;
            fspt += pf.z;
            fcl  += pi.x;
            merge_max(fm, fn1, fn0, pf.w, pi.y, pi.z);
        }
        const float corr = (float)(fn1 + fcl - fn0);
        const float acc  = corr;  // / C with C=1
        const float dice = 2.0f * (fspt + 1.0f) / (fsp + fst + 1.0f);
        const float score = (acc == 1.0f) ? 1.0f : dice;
        v = 1.0f - score;
    }

    // reduce 64 values living in threads 0..63 (warps 0 and 1)
    #pragma unroll
    for (int off = 16; off > 0; off >>= 1)
        v += __shfl_xor_sync(0xffffffffu, v, off);

    __shared__ float sh2[2];
    if (tid < 64 && (tid & 31) == 0) sh2[tid >> 5] = v;
    __syncthreads();

    if (tid == 0) {
        out[0] = (sh2[0] + sh2[1]) / (float)B;
        g_count = 0;  // reset for next graph replay
    }
}

extern "C" void kernel_launch(void* const* d_in, const int* in_sizes, int n_in,
                              void* d_out, int out_size) {
    const float* probs   = (const float*)d_in[0];
    const float* targets = (const float*)d_in[1];
    float* out = (float*)d_out;

    sdl_fused<<<GRID, THREADS>>>(probs, targets, out);
}

// round 12
// speedup vs baseline: 1.1989x; 1.1989x over previous
#include <cuda_runtime.h>
#include <cuda_bf16.h>
#include <math_constants.h>

// SoftDiceLoss: probs [64,1,512,512] f32, targets same. Scalar f32 output.
//
// Fused single-kernel, single-wave version (512 CTAs all co-resident):
// each CTA reduces its slice to a partial, last CTA (threadfence-reduction)
// merges all partials, computes the loss, writes the scalar, resets counter.
//
// Per-sample monoid:
//   sums: sum_p, sum_t, sum_pt, cnt_le (count p<=0.5)
//   max-with-count: (m, d): m = running max of t,
//     d = sum over {t==m} of (p>0.5 ? +1 : -1)   [= n1 - n0]
// Merge: bigger m wins (takes its d); equal m sums d.
// corr = d + cnt_le;  acc = corr / C (C=1);
// dice = 2*(sum_pt+1)/(sum_p+sum_t+1); score = (acc==1) ? 1 : dice;
// loss = mean_b(1 - score).

static constexpr int B        = 64;
static constexpr int NPS      = 512 * 512;   // elements per sample (C=1)
static constexpr int BPS      = 8;           // blocks per sample -> 512 CTAs (ONE wave)
static constexpr int GRID     = B * BPS;
static constexpr int THREADS  = 256;
static constexpr int PER_BLK  = NPS / BPS;            // 32768
static constexpr int VEC_PER_THREAD = PER_BLK / (THREADS * 4);  // 32 float4

// partials: f4 = {sum_p, sum_t, sum_pt, m}, i2 = {cnt_le, d}
__device__ float4 g_pf4[GRID];
__device__ int2   g_pi2[GRID];
__device__ unsigned int g_count = 0;

__device__ __forceinline__ void merge_max(float& m, int& d, float mo, int dd) {
    if (mo > m)       { m = mo; d = dd; }
    else if (mo == m) { d += dd; }
}

__global__ __launch_bounds__(THREADS)
void sdl_fused(const float* __restrict__ probs,
               const float* __restrict__ targets,
               float* __restrict__ out) {
    const int s  = blockIdx.x / BPS;       // sample
    const int bi = blockIdx.x % BPS;       // block within sample
    const int tid = threadIdx.x;

    const float4* p4 = reinterpret_cast<const float4*>(probs   + (size_t)s * NPS + (size_t)bi * PER_BLK);
    const float4* t4 = reinterpret_cast<const float4*>(targets + (size_t)s * NPS + (size_t)bi * PER_BLK);

    float sum_p = 0.f, sum_t = 0.f, sum_pt = 0.f;
    int   cnt_le = 0;
    float m = -CUDART_INF_F;
    int   d = 0;

    #pragma unroll 8
    for (int k = 0; k < VEC_PER_THREAD; k++) {
        float4 pv = p4[tid + k * THREADS];
        float4 tv = t4[tid + k * THREADS];
        const float pa[4] = {pv.x, pv.y, pv.z, pv.w};
        const float ta[4] = {tv.x, tv.y, tv.z, tv.w};
        #pragma unroll
        for (int j = 0; j < 4; j++) {
            float p = pa[j], t = ta[j];
            sum_p  += p;
            sum_t  += t;
            sum_pt += p * t;
            bool sr = (p > 0.5f);
            cnt_le += sr ? 0 : 1;
            bool gt = (t > m);
            m = gt ? t : m;
            d = gt ? 0 : d;
            if (t == m) d += sr ? 1 : -1;
        }
    }

    // warp butterfly reduce
    #pragma unroll
    for (int off = 16; off > 0; off >>= 1) {
        sum_p  += __shfl_xor_sync(0xffffffffu, sum_p,  off);
        sum_t  += __shfl_xor_sync(0xffffffffu, sum_t,  off);
        sum_pt += __shfl_xor_sync(0xffffffffu, sum_pt, off);
        cnt_le += __shfl_xor_sync(0xffffffffu, cnt_le, off);
        float mo = __shfl_xor_sync(0xffffffffu, m, off);
        int   dd = __shfl_xor_sync(0xffffffffu, d, off);
        merge_max(m, d, mo, dd);
    }

    __shared__ float4 shf[THREADS / 32];
    __shared__ int2   shi[THREADS / 32];
    const int wid = tid / 32, lid = tid % 32;
    if (lid == 0) {
        shf[wid] = make_float4(sum_p, sum_t, sum_pt, m);
        shi[wid] = make_int2(cnt_le, d);
    }
    __syncthreads();

    if (wid == 0) {
        constexpr int NW = THREADS / 32;
        float4 af; int2 ai;
        if (lid < NW) { af = shf[lid]; ai = shi[lid]; }
        else { af = make_float4(0.f, 0.f, 0.f, -CUDART_INF_F); ai = make_int2(0, 0); }
        sum_p = af.x; sum_t = af.y; sum_pt = af.z; m = af.w;
        cnt_le = ai.x; d = ai.y;
        #pragma unroll
        for (int off = NW / 2; off > 0; off >>= 1) {
            sum_p  += __shfl_xor_sync(0xffffffffu, sum_p,  off);
            sum_t  += __shfl_xor_sync(0xffffffffu, sum_t,  off);
            sum_pt += __shfl_xor_sync(0xffffffffu, sum_pt, off);
            cnt_le += __shfl_xor_sync(0xffffffffu, cnt_le, off);
            float mo = __shfl_xor_sync(0xffffffffu, m, off);
            int   dd = __shfl_xor_sync(0xffffffffu, d, off);
            merge_max(m, d, mo, dd);
        }
    }

    // ---- publish partial, detect last CTA ----
    __shared__ bool isLast;
    if (tid == 0) {
        g_pf4[blockIdx.x] = make_float4(sum_p, sum_t, sum_pt, m);
        g_pi2[blockIdx.x] = make_int2(cnt_le, d);
        __threadfence();
        unsigned int old = atomicAdd(&g_count, 1u);
        isLast = (old == (unsigned int)(GRID - 1));
    }
    __syncthreads();

    if (!isLast) return;

    // ---- final merge: thread b (<64) merges its sample's 8 partials ----
    __threadfence();  // make other CTAs' partial writes visible

    float v = 0.f;
    const int b = tid;
    if (b < B) {
        float fsp = 0.f, fst = 0.f, fspt = 0.f;
        int   fcl = 0;
        float fm = -CUDART_INF_F;
        int   fd = 0;
        #pragma unroll
        for (int i = 0; i < BPS; i++) {
            float4 pf = __ldcg(&g_pf4[b * BPS + i]);
            int2   pi = __ldcg(&g_pi2[b * BPS + i]);
            fsp  += pf.x;
            fst  += pf.y;
            fspt += pf.z;
            fcl  += pi.x;
            merge_max(fm, fd, pf.w, pi.y);
        }
        const float corr = (float)(fd + fcl);
        const float acc  = corr;  // / C with C=1
        const float dice = 2.0f * (fspt + 1.0f) / (fsp + fst + 1.0f);
        const float score = (acc == 1.0f) ? 1.0f : dice;
        v = 1.0f - score;
    }

    // reduce 64 values living in threads 0..63 (warps 0 and 1)
    #pragma unroll
    for (int off = 16; off > 0; off >>= 1)
        v += __shfl_xor_sync(0xffffffffu, v, off);

    __shared__ float sh2[2];
    if (tid < 64 && (tid & 31) == 0) sh2[tid >> 5] = v;
    __syncthreads();

    if (tid == 0) {
        out[0] = (sh2[0] + sh2[1]) / (float)B;
        g_count = 0;  // reset for next graph replay
    }
}

extern "C" void kernel_launch(void* const* d_in, const int* in_sizes, int n_in,
                              void* d_out, int out_size) {
    const float* probs   = (const float*)d_in[0];
    const float* targets = (const float*)d_in[1];
    float* out = (float*)d_out;

    sdl_fused<<<GRID, THREADS>>>(probs, targets, out);
}